// round 2
// baseline (speedup 1.0000x reference)
#include <cuda_runtime.h>
#include <cstdint>
#include <cstddef>

// Problem constants (fixed by the dataset)
#define BB 16
#define MM 16
#define JXN 128
#define JQN 64
#define DN 256

// Scratch for per-row max(s over q) + s_h  (p-softmax input), B*M*JX floats
__device__ float g_rowmax[BB * MM * JXN];

// shared memory layout strides (floats)
constexpr int UT_S   = 68;   // u_t  [256][68]  (u transposed: [d][q])
constexpr int USM_S  = 260;  // u_sm [64][260]  (u row-major:  [q][d])
constexpr int AS2_S  = 68;   // A2   [64][68]   (h*w3 chunk, DUPLICATED pairs, k-chunk=32)
constexpr int AT2_S  = 130;  // a_t2 [64][130]  (softmaxed attention transposed, DUPLICATED pairs)

constexpr int SMEM_FLOATS = 256*UT_S + 64*USM_S + 64*AS2_S + 64*AT2_S + 3*DN + 64 + 64;

// ---- packed fp32x2 helpers (sm_100+; ptxas never auto-fuses these) ----
__device__ __forceinline__ void ffma2(unsigned long long& d,
                                      const unsigned long long a,
                                      const unsigned long long b) {
    asm("fma.rn.f32x2 %0, %1, %2, %0;" : "+l"(d) : "l"(a), "l"(b));
}
__device__ __forceinline__ float2 unpack2(const unsigned long long v) {
    float2 r;
    asm("mov.b64 {%0, %1}, %2;" : "=f"(r.x), "=f"(r.y) : "l"(v));
    return r;
}

// ---------------------------------------------------------------------------
// Kernel 1: per CTA = one (b,m) pair, one 64-row half of JX.
//  - GEMM1: C[j,q] = sum_d (h[j,d]*w3[d]) * u[q,d]           (64x64x256)
//  - softmax over q of (C + s_u)  -> a_t2 ;  rowmax+s_h -> scratch
//  - GEMM2: u_att[j,d] = sum_q a[j,q]*u[q,d]                 (64x256x64)
//  - writes out segments: [0:D)=h, [D:2D)=u_att, [2D:3D)=h*u_att
// ---------------------------------------------------------------------------
__global__ void __launch_bounds__(256, 1)
attn_k1(const float* __restrict__ hg, const float* __restrict__ ug,
        const float* __restrict__ wg, float* __restrict__ out)
{
    extern __shared__ float sm[];
    float* u_t  = sm;                      // 256*68
    float* u_sm = u_t  + 256 * UT_S;       // 64*260
    float* A2   = u_sm + 64  * USM_S;      // 64*68  (duplicated A chunk)
    float* a_t2 = A2   + 64  * AS2_S;      // 64*130 (duplicated attention)
    float* w_s  = a_t2 + 64  * AT2_S;      // 768  (w1|w2|w3)
    float* s_u  = w_s  + 3 * DN;           // 64
    float* s_h  = s_u  + 64;               // 64

    const int tid = threadIdx.x;
    const int bm  = blockIdx.x >> 1;
    const int j0  = (blockIdx.x & 1) * 64;
    const int b   = bm >> 4;

    const float* __restrict__ hrow = hg + (size_t)(bm * JXN + j0) * DN;
    const float* __restrict__ ub   = ug + (size_t)b * JQN * DN;

    // ---- load w into smem ----
    for (int i = tid; i < 3 * DN; i += 256) w_s[i] = wg[i];

    // ---- fill u_sm (row-major copy of u[b], coalesced) ----
    for (int idx = tid; idx < JQN * (DN / 4); idx += 256) {
        int q = idx >> 6, d4 = idx & 63;
        float4 v = *(const float4*)(ub + q * DN + d4 * 4);
        *(float4*)(u_sm + q * USM_S + d4 * 4) = v;
    }
    // ---- fill u_t (transposed [d][q]) ----
    for (int idx = tid; idx < (DN / 4) * JQN; idx += 256) {
        int d4 = idx >> 6, q = idx & 63;
        float4 v = *(const float4*)(ub + q * DN + d4 * 4);
        u_t[(d4 * 4 + 0) * UT_S + q] = v.x;
        u_t[(d4 * 4 + 1) * UT_S + q] = v.y;
        u_t[(d4 * 4 + 2) * UT_S + q] = v.z;
        u_t[(d4 * 4 + 3) * UT_S + q] = v.w;
    }
    __syncthreads();

    // ---- s_u[q] = u[q,:] . w2  (conflict-free via u_t) ----
    if (tid < 64) {
        float acc = 0.f;
        #pragma unroll 8
        for (int k = 0; k < DN; k++) acc += u_t[k * UT_S + tid] * w_s[DN + k];
        s_u[tid] = acc;
    }

    const int ty = tid >> 4, tx = tid & 15;   // thread tile: rows 4*ty.., q 4*tx..
    const int row_a = tid >> 3;               // staging: rows row_a, row_a+32
    const int k4a   = (tid & 7) * 4;          // staging: 4 k's within chunk

    unsigned long long c1p[4][2];
    #pragma unroll
    for (int r = 0; r < 4; r++) { c1p[r][0] = 0ULL; c1p[r][1] = 0ULL; }

    float sh0 = 0.f, sh1 = 0.f;   // partial h.w1 for rows row_a, row_a+32

    // prefetch chunk 0 of A (h rows) into registers
    float4 pa0 = *(const float4*)(hrow + row_a * DN + k4a);
    float4 pa1 = *(const float4*)(hrow + (row_a + 32) * DN + k4a);

    // ---- GEMM1 main loop: 8 k-chunks of 32 ----
    for (int c = 0; c < 8; c++) {
        const int kc = c * 32;
        // s_h partials (w1) computed from raw h
        sh0 += pa0.x * w_s[kc + k4a + 0] + pa0.y * w_s[kc + k4a + 1]
             + pa0.z * w_s[kc + k4a + 2] + pa0.w * w_s[kc + k4a + 3];
        sh1 += pa1.x * w_s[kc + k4a + 0] + pa1.y * w_s[kc + k4a + 1]
             + pa1.z * w_s[kc + k4a + 2] + pa1.w * w_s[kc + k4a + 3];
        // scale by w3 and stage DUPLICATED pairs to smem
        const float* w3 = w_s + 2 * DN + kc + k4a;
        float4 t0, t1;
        t0.x = pa0.x * w3[0]; t0.y = pa0.y * w3[1]; t0.z = pa0.z * w3[2]; t0.w = pa0.w * w3[3];
        t1.x = pa1.x * w3[0]; t1.y = pa1.y * w3[1]; t1.z = pa1.z * w3[2]; t1.w = pa1.w * w3[3];
        *(float4*)(A2 + row_a * AS2_S + 2 * k4a)            = make_float4(t0.x, t0.x, t0.y, t0.y);
        *(float4*)(A2 + row_a * AS2_S + 2 * k4a + 4)        = make_float4(t0.z, t0.z, t0.w, t0.w);
        *(float4*)(A2 + (row_a + 32) * AS2_S + 2 * k4a)     = make_float4(t1.x, t1.x, t1.y, t1.y);
        *(float4*)(A2 + (row_a + 32) * AS2_S + 2 * k4a + 4) = make_float4(t1.z, t1.z, t1.w, t1.w);
        __syncthreads();
        // prefetch next chunk (hides LDG latency under compute)
        if (c < 7) {
            pa0 = *(const float4*)(hrow + row_a * DN + kc + 32 + k4a);
            pa1 = *(const float4*)(hrow + (row_a + 32) * DN + kc + 32 + k4a);
        }
        // packed 4x(2x2) FFMA2 tile over this k-chunk
        #pragma unroll 8
        for (int kk = 0; kk < 32; kk++) {
            ulonglong2 bbp = *(const ulonglong2*)(u_t + (kc + kk) * UT_S + tx * 4);
            #pragma unroll
            for (int r = 0; r < 4; r++) {
                unsigned long long ad =
                    *(const unsigned long long*)(A2 + (ty * 4 + r) * AS2_S + 2 * kk);
                ffma2(c1p[r][0], ad, bbp.x);
                ffma2(c1p[r][1], ad, bbp.y);
            }
        }
        __syncthreads();
    }

    // ---- reduce s_h partials over the 8 lanes sharing a row ----
    #pragma unroll
    for (int o = 4; o >= 1; o >>= 1) {
        sh0 += __shfl_down_sync(0xffffffffu, sh0, o, 8);
        sh1 += __shfl_down_sync(0xffffffffu, sh1, o, 8);
    }
    if ((tid & 7) == 0) { s_h[row_a] = sh0; s_h[row_a + 32] = sh1; }
    __syncthreads();

    // ---- epilogue: softmax over q (s_h and bias cancel), write a_t2 + rowmax ----
    #pragma unroll
    for (int r = 0; r < 4; r++) {
        const int row = ty * 4 + r;
        float2 p01 = unpack2(c1p[r][0]);
        float2 p23 = unpack2(c1p[r][1]);
        float v0 = p01.x + s_u[tx * 4 + 0];
        float v1 = p01.y + s_u[tx * 4 + 1];
        float v2 = p23.x + s_u[tx * 4 + 2];
        float v3 = p23.y + s_u[tx * 4 + 3];
        float mx = fmaxf(fmaxf(v0, v1), fmaxf(v2, v3));
        #pragma unroll
        for (int o = 8; o >= 1; o >>= 1) mx = fmaxf(mx, __shfl_xor_sync(0xffffffffu, mx, o, 16));
        float e0 = __expf(v0 - mx), e1 = __expf(v1 - mx);
        float e2 = __expf(v2 - mx), e3 = __expf(v3 - mx);
        float sum = e0 + e1 + e2 + e3;
        #pragma unroll
        for (int o = 8; o >= 1; o >>= 1) sum += __shfl_xor_sync(0xffffffffu, sum, o, 16);
        float inv = 1.f / sum;
        float a0 = e0 * inv, a1 = e1 * inv, a2 = e2 * inv, a3 = e3 * inv;
        *(float2*)(a_t2 + (tx * 4 + 0) * AT2_S + 2 * row) = make_float2(a0, a0);
        *(float2*)(a_t2 + (tx * 4 + 1) * AT2_S + 2 * row) = make_float2(a1, a1);
        *(float2*)(a_t2 + (tx * 4 + 2) * AT2_S + 2 * row) = make_float2(a2, a2);
        *(float2*)(a_t2 + (tx * 4 + 3) * AT2_S + 2 * row) = make_float2(a3, a3);
        if (tx == 0) g_rowmax[bm * JXN + j0 + row] = mx + s_h[row];
    }
    __syncthreads();

    // ---- GEMM2 (u_att, packed) + write segments 0..2 ----
    const size_t outbase = (size_t)(bm * JXN + j0) * (4 * DN);
    for (int p = 0; p < 4; p++) {
        unsigned long long c2p[4][2];
        #pragma unroll
        for (int r = 0; r < 4; r++) { c2p[r][0] = 0ULL; c2p[r][1] = 0ULL; }
        #pragma unroll 8
        for (int k = 0; k < 64; k++) {
            ulonglong2 bbp = *(const ulonglong2*)(u_sm + k * USM_S + p * 64 + tx * 4);
            #pragma unroll
            for (int r = 0; r < 4; r++) {
                unsigned long long ad =
                    *(const unsigned long long*)(a_t2 + k * AT2_S + 2 * (ty * 4 + r));
                ffma2(c2p[r][0], ad, bbp.x);
                ffma2(c2p[r][1], ad, bbp.y);
            }
        }
        #pragma unroll
        for (int r = 0; r < 4; r++) {
            const int row = ty * 4 + r;
            const int dg  = p * 64 + tx * 4;
            float4 h4 = *(const float4*)(hrow + row * DN + dg);   // L2-hot reload
            float2 u01 = unpack2(c2p[r][0]);
            float2 u23 = unpack2(c2p[r][1]);
            float4 ua = make_float4(u01.x, u01.y, u23.x, u23.y);
            float4 hu = make_float4(h4.x * ua.x, h4.y * ua.y, h4.z * ua.z, h4.w * ua.w);
            float* ob = out + outbase + (size_t)row * (4 * DN);
            *(float4*)(ob + dg)           = h4;   // segment 0: h
            *(float4*)(ob + DN + dg)      = ua;   // segment 1: u_att
            *(float4*)(ob + 2 * DN + dg)  = hu;   // segment 2: h*u_att
        }
    }
}

// ---------------------------------------------------------------------------
// Kernel 2: per CTA = one (b,m, d-half). p = softmax_j(rowmax);
// h_att = sum_j p_j h_j; writes segment 3: h * h_att (broadcast over j).
// ---------------------------------------------------------------------------
__global__ void __launch_bounds__(256)
attn_k2(const float* __restrict__ hg, float* __restrict__ out)
{
    __shared__ float  p_s[JXN];
    __shared__ float4 part[8][32];

    const int bm  = blockIdx.x >> 1;
    const int dh  = (blockIdx.x & 1) * 128;
    const int tid = threadIdx.x;
    const float* __restrict__ hb = hg + (size_t)bm * JXN * DN;

    if (tid < 32) {
        float v0 = g_rowmax[bm * JXN + tid];
        float v1 = g_rowmax[bm * JXN + tid + 32];
        float v2 = g_rowmax[bm * JXN + tid + 64];
        float v3 = g_rowmax[bm * JXN + tid + 96];
        float mx = fmaxf(fmaxf(v0, v1), fmaxf(v2, v3));
        #pragma unroll
        for (int o = 16; o >= 1; o >>= 1) mx = fmaxf(mx, __shfl_xor_sync(0xffffffffu, mx, o));
        float e0 = __expf(v0 - mx), e1 = __expf(v1 - mx);
        float e2 = __expf(v2 - mx), e3 = __expf(v3 - mx);
        float s = e0 + e1 + e2 + e3;
        #pragma unroll
        for (int o = 16; o >= 1; o >>= 1) s += __shfl_xor_sync(0xffffffffu, s, o);
        float inv = 1.f / s;
        p_s[tid]      = e0 * inv;
        p_s[tid + 32] = e1 * inv;
        p_s[tid + 64] = e2 * inv;
        p_s[tid + 96] = e3 * inv;
    }
    __syncthreads();

    const int jg = tid >> 5, dq = tid & 31;   // 8 j-groups x 16 j; 32 float4 slots
    const int dof = dh + dq * 4;

    float4 acc = make_float4(0.f, 0.f, 0.f, 0.f);
    #pragma unroll 4
    for (int j = jg * 16; j < jg * 16 + 16; j++) {
        float4 hv = *(const float4*)(hb + j * DN + dof);
        float pj = p_s[j];
        acc.x += pj * hv.x; acc.y += pj * hv.y; acc.z += pj * hv.z; acc.w += pj * hv.w;
    }
    part[jg][dq] = acc;
    __syncthreads();
    if (tid < 32) {
        float4 s = part[0][tid];
        #pragma unroll
        for (int g = 1; g < 8; g++) {
            float4 v = part[g][tid];
            s.x += v.x; s.y += v.y; s.z += v.z; s.w += v.w;
        }
        part[0][tid] = s;
    }
    __syncthreads();
    const float4 ha = part[0][dq];
    #pragma unroll 2
    for (int j = jg * 16; j < jg * 16 + 16; j++) {
        float4 hv = *(const float4*)(hb + j * DN + dof);   // L1-hot second read
        float4 o;
        o.x = hv.x * ha.x; o.y = hv.y * ha.y; o.z = hv.z * ha.z; o.w = hv.w * ha.w;
        *(float4*)(out + (size_t)(bm * JXN + j) * (4 * DN) + 3 * DN + dof) = o;
    }
}

// ---------------------------------------------------------------------------
extern "C" void kernel_launch(void* const* d_in, const int* in_sizes, int n_in,
                              void* d_out, int out_size)
{
    (void)in_sizes; (void)n_in; (void)out_size;
    const float* h = (const float*)d_in[0];
    const float* u = (const float*)d_in[1];
    const float* w = (const float*)d_in[2];
    // d_in[3] is the scalar bias b: it cancels in both softmaxes -> unused.
    float* out = (float*)d_out;

    const size_t smem = SMEM_FLOATS * sizeof(float);  // ~190 KB
    cudaFuncSetAttribute(attn_k1, cudaFuncAttributeMaxDynamicSharedMemorySize, (int)smem);

    attn_k1<<<BB * MM * 2, 256, smem>>>(h, u, w, out);
    attn_k2<<<BB * MM * 2, 256>>>(h, out);
}

// round 3
// speedup vs baseline: 1.0221x; 1.0221x over previous
#include <cuda_runtime.h>
#include <cstdint>
#include <cstddef>

// Problem constants (fixed by the dataset)
#define BB 16
#define MM 16
#define JXN 128
#define JQN 64
#define DN 256

// Scratch for per-row max(s over q) + s_h  (p-softmax input), B*M*JX floats
__device__ float g_rowmax[BB * MM * JXN];

// shared memory layout strides (floats)
constexpr int UT_S  = 68;   // u_t  [256][68]  (u transposed: [d][q])
constexpr int USM_S = 260;  // u_sm [64][260]  (u row-major:  [q][d])
constexpr int ATR_S = 68;   // A_t  [2][32][68] (h*w3 chunk, TRANSPOSED [k][j], double-buffered)
constexpr int AT_S  = 68;   // a_t  [64][68]   (softmaxed attention transposed [q][j])

constexpr int SMEM_FLOATS = 256*UT_S + 64*USM_S + 2*32*ATR_S + 64*AT_S + 3*DN + 64 + 64;

// ---------------------------------------------------------------------------
// Kernel 1: per CTA = one (b,m) pair, one 64-row half of JX.
//  - GEMM1: C[j,q] = sum_d (h[j,d]*w3[d]) * u[q,d]           (64x64x256)
//  - softmax over q of (C + s_u)  -> a_t ;  rowmax+s_h -> scratch
//  - GEMM2: u_att[j,d] = sum_q a[j,q]*u[q,d]                 (64x256x64)
//  - writes out segments: [0:D)=h, [D:2D)=u_att, [2D:3D)=h*u_att
// ---------------------------------------------------------------------------
__global__ void __launch_bounds__(256, 1)
attn_k1(const float* __restrict__ hg, const float* __restrict__ ug,
        const float* __restrict__ wg, float* __restrict__ out)
{
    extern __shared__ float sm[];
    float* u_t  = sm;                      // 256*68
    float* u_sm = u_t  + 256 * UT_S;       // 64*260
    float* A_t  = u_sm + 64  * USM_S;      // 2*32*68  (transposed A chunk, double buffer)
    float* a_t  = A_t  + 2 * 32 * ATR_S;   // 64*68
    float* w_s  = a_t  + 64  * AT_S;       // 768  (w1|w2|w3)
    float* s_u  = w_s  + 3 * DN;           // 64
    float* s_h  = s_u  + 64;               // 64

    const int tid = threadIdx.x;
    const int bm  = blockIdx.x >> 1;
    const int j0  = (blockIdx.x & 1) * 64;
    const int b   = bm >> 4;

    const float* __restrict__ hrow = hg + (size_t)(bm * JXN + j0) * DN;
    const float* __restrict__ ub   = ug + (size_t)b * JQN * DN;

    // ---- load w into smem ----
    for (int i = tid; i < 3 * DN; i += 256) w_s[i] = wg[i];

    // ---- fill u_sm (row-major copy of u[b], coalesced) ----
    for (int idx = tid; idx < JQN * (DN / 4); idx += 256) {
        int q = idx >> 6, d4 = idx & 63;
        float4 v = *(const float4*)(ub + q * DN + d4 * 4);
        *(float4*)(u_sm + q * USM_S + d4 * 4) = v;
    }
    // ---- fill u_t (transposed [d][q]) ----
    for (int idx = tid; idx < (DN / 4) * JQN; idx += 256) {
        int d4 = idx >> 6, q = idx & 63;
        float4 v = *(const float4*)(ub + q * DN + d4 * 4);
        u_t[(d4 * 4 + 0) * UT_S + q] = v.x;
        u_t[(d4 * 4 + 1) * UT_S + q] = v.y;
        u_t[(d4 * 4 + 2) * UT_S + q] = v.z;
        u_t[(d4 * 4 + 3) * UT_S + q] = v.w;
    }
    __syncthreads();

    // ---- s_u[q] = u[q,:] . w2  (conflict-free via u_t) ----
    if (tid < 64) {
        float acc = 0.f;
        #pragma unroll 8
        for (int k = 0; k < DN; k++) acc += u_t[k * UT_S + tid] * w_s[DN + k];
        s_u[tid] = acc;
    }

    const int ty = tid >> 4, tx = tid & 15;   // thread tile: rows 4*ty.., q 4*tx..
    const int row_a = tid >> 3;               // staging: rows row_a, row_a+32
    const int k4a   = (tid & 7) * 4;          // staging: 4 k's within chunk

    float c1[4][4];
    #pragma unroll
    for (int r = 0; r < 4; r++)
        #pragma unroll
        for (int j = 0; j < 4; j++) c1[r][j] = 0.f;

    float sh0 = 0.f, sh1 = 0.f;   // partial h.w1 for rows row_a, row_a+32

    // ---- stage chunk 0 (h*w3, transposed into A_t buf 0) ----
    {
        float4 pa0 = *(const float4*)(hrow + row_a * DN + k4a);
        float4 pa1 = *(const float4*)(hrow + (row_a + 32) * DN + k4a);
        sh0 += pa0.x * w_s[k4a + 0] + pa0.y * w_s[k4a + 1]
             + pa0.z * w_s[k4a + 2] + pa0.w * w_s[k4a + 3];
        sh1 += pa1.x * w_s[k4a + 0] + pa1.y * w_s[k4a + 1]
             + pa1.z * w_s[k4a + 2] + pa1.w * w_s[k4a + 3];
        const float* w3 = w_s + 2 * DN + k4a;
        float* At = A_t;  // buffer 0
        At[(k4a + 0) * ATR_S + row_a] = pa0.x * w3[0];
        At[(k4a + 1) * ATR_S + row_a] = pa0.y * w3[1];
        At[(k4a + 2) * ATR_S + row_a] = pa0.z * w3[2];
        At[(k4a + 3) * ATR_S + row_a] = pa0.w * w3[3];
        At[(k4a + 0) * ATR_S + row_a + 32] = pa1.x * w3[0];
        At[(k4a + 1) * ATR_S + row_a + 32] = pa1.y * w3[1];
        At[(k4a + 2) * ATR_S + row_a + 32] = pa1.z * w3[2];
        At[(k4a + 3) * ATR_S + row_a + 32] = pa1.w * w3[3];
    }
    __syncthreads();

    // ---- GEMM1 main loop: 8 k-chunks of 32, double-buffered (1 sync/chunk) ----
    for (int c = 0; c < 8; c++) {
        const int kc = c * 32;
        const float* Acur = A_t + (c & 1) * 32 * ATR_S;

        // stage chunk c+1 into the other buffer (overlaps with compute below)
        if (c < 7) {
            const int kn = kc + 32;
            float4 pa0 = *(const float4*)(hrow + row_a * DN + kn + k4a);
            float4 pa1 = *(const float4*)(hrow + (row_a + 32) * DN + kn + k4a);
            sh0 += pa0.x * w_s[kn + k4a + 0] + pa0.y * w_s[kn + k4a + 1]
                 + pa0.z * w_s[kn + k4a + 2] + pa0.w * w_s[kn + k4a + 3];
            sh1 += pa1.x * w_s[kn + k4a + 0] + pa1.y * w_s[kn + k4a + 1]
                 + pa1.z * w_s[kn + k4a + 2] + pa1.w * w_s[kn + k4a + 3];
            const float* w3 = w_s + 2 * DN + kn + k4a;
            float* An = A_t + ((c + 1) & 1) * 32 * ATR_S;
            An[(k4a + 0) * ATR_S + row_a] = pa0.x * w3[0];
            An[(k4a + 1) * ATR_S + row_a] = pa0.y * w3[1];
            An[(k4a + 2) * ATR_S + row_a] = pa0.z * w3[2];
            An[(k4a + 3) * ATR_S + row_a] = pa0.w * w3[3];
            An[(k4a + 0) * ATR_S + row_a + 32] = pa1.x * w3[0];
            An[(k4a + 1) * ATR_S + row_a + 32] = pa1.y * w3[1];
            An[(k4a + 2) * ATR_S + row_a + 32] = pa1.z * w3[2];
            An[(k4a + 3) * ATR_S + row_a + 32] = pa1.w * w3[3];
        }

        // register-tiled 4x4 FMA; BOTH operands contiguous LDS.128 (conflict-free)
        #pragma unroll 8
        for (int kk = 0; kk < 32; kk++) {
            float4 aa = *(const float4*)(Acur + kk * ATR_S + ty * 4);
            float4 bb = *(const float4*)(u_t + (kc + kk) * UT_S + tx * 4);
            c1[0][0] += aa.x * bb.x; c1[0][1] += aa.x * bb.y; c1[0][2] += aa.x * bb.z; c1[0][3] += aa.x * bb.w;
            c1[1][0] += aa.y * bb.x; c1[1][1] += aa.y * bb.y; c1[1][2] += aa.y * bb.z; c1[1][3] += aa.y * bb.w;
            c1[2][0] += aa.z * bb.x; c1[2][1] += aa.z * bb.y; c1[2][2] += aa.z * bb.z; c1[2][3] += aa.z * bb.w;
            c1[3][0] += aa.w * bb.x; c1[3][1] += aa.w * bb.y; c1[3][2] += aa.w * bb.z; c1[3][3] += aa.w * bb.w;
        }
        __syncthreads();
    }

    // ---- reduce s_h partials over the 8 lanes sharing a row ----
    #pragma unroll
    for (int o = 4; o >= 1; o >>= 1) {
        sh0 += __shfl_down_sync(0xffffffffu, sh0, o, 8);
        sh1 += __shfl_down_sync(0xffffffffu, sh1, o, 8);
    }
    if ((tid & 7) == 0) { s_h[row_a] = sh0; s_h[row_a + 32] = sh1; }
    __syncthreads();

    // ---- epilogue: softmax over q (s_h and bias cancel), write a_t + rowmax ----
    // NOTE: c1[r] holds row 4*ty+r, cols 4*tx..4*tx+3 (q). Here tile cols come
    // from u_t[.. + tx*4], rows from A_t[.. + ty*4] => row=4*ty+r is the j index.
    #pragma unroll
    for (int r = 0; r < 4; r++) {
        const int row = ty * 4 + r;
        float v0 = c1[r][0] + s_u[tx * 4 + 0];
        float v1 = c1[r][1] + s_u[tx * 4 + 1];
        float v2 = c1[r][2] + s_u[tx * 4 + 2];
        float v3 = c1[r][3] + s_u[tx * 4 + 3];
        float mx = fmaxf(fmaxf(v0, v1), fmaxf(v2, v3));
        #pragma unroll
        for (int o = 8; o >= 1; o >>= 1) mx = fmaxf(mx, __shfl_xor_sync(0xffffffffu, mx, o, 16));
        float e0 = __expf(v0 - mx), e1 = __expf(v1 - mx);
        float e2 = __expf(v2 - mx), e3 = __expf(v3 - mx);
        float sum = e0 + e1 + e2 + e3;
        #pragma unroll
        for (int o = 8; o >= 1; o >>= 1) sum += __shfl_xor_sync(0xffffffffu, sum, o, 16);
        float inv = 1.f / sum;
        a_t[(tx * 4 + 0) * AT_S + row] = e0 * inv;
        a_t[(tx * 4 + 1) * AT_S + row] = e1 * inv;
        a_t[(tx * 4 + 2) * AT_S + row] = e2 * inv;
        a_t[(tx * 4 + 3) * AT_S + row] = e3 * inv;
        if (tx == 0) g_rowmax[bm * JXN + j0 + row] = mx + s_h[row];
    }
    __syncthreads();

    // ---- GEMM2 (u_att) + write segments 0..2  (both operands conflict-free) ----
    const size_t outbase = (size_t)(bm * JXN + j0) * (4 * DN);
    for (int p = 0; p < 4; p++) {
        float c2[4][4];
        #pragma unroll
        for (int r = 0; r < 4; r++)
            #pragma unroll
            for (int j = 0; j < 4; j++) c2[r][j] = 0.f;
        #pragma unroll 8
        for (int k = 0; k < 64; k++) {
            float4 aa = *(const float4*)(a_t + k * AT_S + ty * 4);
            float4 bb = *(const float4*)(u_sm + k * USM_S + p * 64 + tx * 4);
            c2[0][0] += aa.x * bb.x; c2[0][1] += aa.x * bb.y; c2[0][2] += aa.x * bb.z; c2[0][3] += aa.x * bb.w;
            c2[1][0] += aa.y * bb.x; c2[1][1] += aa.y * bb.y; c2[1][2] += aa.y * bb.z; c2[1][3] += aa.y * bb.w;
            c2[2][0] += aa.z * bb.x; c2[2][1] += aa.z * bb.y; c2[2][2] += aa.z * bb.z; c2[2][3] += aa.z * bb.w;
            c2[3][0] += aa.w * bb.x; c2[3][1] += aa.w * bb.y; c2[3][2] += aa.w * bb.z; c2[3][3] += aa.w * bb.w;
        }
        #pragma unroll
        for (int r = 0; r < 4; r++) {
            const int row = ty * 4 + r;
            const int dg  = p * 64 + tx * 4;
            float4 h4 = *(const float4*)(hrow + row * DN + dg);   // L2-hot reload
            float4 ua = make_float4(c2[r][0], c2[r][1], c2[r][2], c2[r][3]);
            float4 hu = make_float4(h4.x * ua.x, h4.y * ua.y, h4.z * ua.z, h4.w * ua.w);
            float* ob = out + outbase + (size_t)row * (4 * DN);
            *(float4*)(ob + dg)           = h4;   // segment 0: h
            *(float4*)(ob + DN + dg)      = ua;   // segment 1: u_att
            *(float4*)(ob + 2 * DN + dg)  = hu;   // segment 2: h*u_att
        }
    }
}

// ---------------------------------------------------------------------------
// Kernel 2: per CTA = one (b,m, d-half). p = softmax_j(rowmax);
// h_att = sum_j p_j h_j; writes segment 3: h * h_att (broadcast over j).
// ---------------------------------------------------------------------------
__global__ void __launch_bounds__(256)
attn_k2(const float* __restrict__ hg, float* __restrict__ out)
{
    __shared__ float  p_s[JXN];
    __shared__ float4 part[8][32];

    const int bm  = blockIdx.x >> 1;
    const int dh  = (blockIdx.x & 1) * 128;
    const int tid = threadIdx.x;
    const float* __restrict__ hb = hg + (size_t)bm * JXN * DN;

    if (tid < 32) {
        float v0 = g_rowmax[bm * JXN + tid];
        float v1 = g_rowmax[bm * JXN + tid + 32];
        float v2 = g_rowmax[bm * JXN + tid + 64];
        float v3 = g_rowmax[bm * JXN + tid + 96];
        float mx = fmaxf(fmaxf(v0, v1), fmaxf(v2, v3));
        #pragma unroll
        for (int o = 16; o >= 1; o >>= 1) mx = fmaxf(mx, __shfl_xor_sync(0xffffffffu, mx, o));
        float e0 = __expf(v0 - mx), e1 = __expf(v1 - mx);
        float e2 = __expf(v2 - mx), e3 = __expf(v3 - mx);
        float s = e0 + e1 + e2 + e3;
        #pragma unroll
        for (int o = 16; o >= 1; o >>= 1) s += __shfl_xor_sync(0xffffffffu, s, o);
        float inv = 1.f / s;
        p_s[tid]      = e0 * inv;
        p_s[tid + 32] = e1 * inv;
        p_s[tid + 64] = e2 * inv;
        p_s[tid + 96] = e3 * inv;
    }
    __syncthreads();

    const int jg = tid >> 5, dq = tid & 31;   // 8 j-groups x 16 j; 32 float4 slots
    const int dof = dh + dq * 4;

    float4 acc = make_float4(0.f, 0.f, 0.f, 0.f);
    #pragma unroll 4
    for (int j = jg * 16; j < jg * 16 + 16; j++) {
        float4 hv = *(const float4*)(hb + j * DN + dof);
        float pj = p_s[j];
        acc.x += pj * hv.x; acc.y += pj * hv.y; acc.z += pj * hv.z; acc.w += pj * hv.w;
    }
    part[jg][dq] = acc;
    __syncthreads();
    if (tid < 32) {
        float4 s = part[0][tid];
        #pragma unroll
        for (int g = 1; g < 8; g++) {
            float4 v = part[g][tid];
            s.x += v.x; s.y += v.y; s.z += v.z; s.w += v.w;
        }
        part[0][tid] = s;
    }
    __syncthreads();
    const float4 ha = part[0][dq];
    #pragma unroll 2
    for (int j = jg * 16; j < jg * 16 + 16; j++) {
        float4 hv = *(const float4*)(hb + j * DN + dof);   // L1-hot second read
        float4 o;
        o.x = hv.x * ha.x; o.y = hv.y * ha.y; o.z = hv.z * ha.z; o.w = hv.w * ha.w;
        *(float4*)(out + (size_t)(bm * JXN + j) * (4 * DN) + 3 * DN + dof) = o;
    }
}

// ---------------------------------------------------------------------------
extern "C" void kernel_launch(void* const* d_in, const int* in_sizes, int n_in,
                              void* d_out, int out_size)
{
    (void)in_sizes; (void)n_in; (void)out_size;
    const float* h = (const float*)d_in[0];
    const float* u = (const float*)d_in[1];
    const float* w = (const float*)d_in[2];
    // d_in[3] is the scalar bias b: it cancels in both softmaxes -> unused.
    float* out = (float*)d_out;

    const size_t smem = SMEM_FLOATS * sizeof(float);  // ~166 KB
    cudaFuncSetAttribute(attn_k1, cudaFuncAttributeMaxDynamicSharedMemorySize, (int)smem);

    attn_k1<<<BB * MM * 2, 256, smem>>>(h, u, w, out);
    attn_k2<<<BB * MM * 2, 256>>>(h, out);
}

// round 4
// speedup vs baseline: 1.0241x; 1.0020x over previous
#include <cuda_runtime.h>
#include <cstdint>
#include <cstddef>

// Problem constants (fixed by the dataset)
#define BB 16
#define MM 16
#define JXN 128
#define JQN 64
#define DN 256

// Scratch for per-row max(s over q) + s_h  (p-softmax input), B*M*JX floats
__device__ float g_rowmax[BB * MM * JXN];

// shared memory layout strides (floats)
constexpr int UT_S  = 68;   // u_t  [256][68]  (u transposed: [d][q])
constexpr int USM_S = 260;  // u_sm [64][260]  (u row-major:  [q][d])
constexpr int ATR_S = 68;   // A_t  [2][32][68] (h*w3 chunk, TRANSPOSED [k][j], double-buffered)
constexpr int AT_S  = 68;   // a_t  [64][68]   (softmaxed attention transposed [q][j])

constexpr int SMEM_FLOATS = 256*UT_S + 64*USM_S + 2*32*ATR_S + 64*AT_S + 3*DN + 64 + 64;

// ---------------------------------------------------------------------------
// Kernel 1: per CTA = one (b,m) pair, one 64-row half of JX.
//  - GEMM1: C[j,q] = sum_d (h[j,d]*w3[d]) * u[q,d]           (64x64x256)
//  - softmax over q of (C + s_u)  -> a_t ;  rowmax+s_h -> scratch
//  - GEMM2: u_att[j,d] = sum_q a[j,q]*u[q,d]                 (64x256x64)
//  - writes out segments: [0:D)=h, [D:2D)=u_att, [2D:3D)=h*u_att
// ---------------------------------------------------------------------------
__global__ void __launch_bounds__(256, 1)
attn_k1(const float* __restrict__ hg, const float* __restrict__ ug,
        const float* __restrict__ wg, float* __restrict__ out)
{
    extern __shared__ float sm[];
    float* u_t  = sm;                      // 256*68
    float* u_sm = u_t  + 256 * UT_S;       // 64*260
    float* A_t  = u_sm + 64  * USM_S;      // 2*32*68  (transposed A chunk, double buffer)
    float* a_t  = A_t  + 2 * 32 * ATR_S;   // 64*68
    float* w_s  = a_t  + 64  * AT_S;       // 768  (w1|w2|w3)
    float* s_u  = w_s  + 3 * DN;           // 64
    float* s_h  = s_u  + 64;               // 64

    const int tid = threadIdx.x;
    const int bm  = blockIdx.x >> 1;
    const int j0  = (blockIdx.x & 1) * 64;
    const int b   = bm >> 4;

    const float* __restrict__ hrow = hg + (size_t)(bm * JXN + j0) * DN;
    const float* __restrict__ ub   = ug + (size_t)b * JQN * DN;

    // ---- load w into smem ----
    for (int i = tid; i < 3 * DN; i += 256) w_s[i] = wg[i];

    // ---- fill u_sm (row-major copy of u[b], coalesced) ----
    for (int idx = tid; idx < JQN * (DN / 4); idx += 256) {
        int q = idx >> 6, d4 = idx & 63;
        float4 v = *(const float4*)(ub + q * DN + d4 * 4);
        *(float4*)(u_sm + q * USM_S + d4 * 4) = v;
    }
    // ---- fill u_t (transposed [d][q]) ----
    for (int idx = tid; idx < (DN / 4) * JQN; idx += 256) {
        int d4 = idx >> 6, q = idx & 63;
        float4 v = *(const float4*)(ub + q * DN + d4 * 4);
        u_t[(d4 * 4 + 0) * UT_S + q] = v.x;
        u_t[(d4 * 4 + 1) * UT_S + q] = v.y;
        u_t[(d4 * 4 + 2) * UT_S + q] = v.z;
        u_t[(d4 * 4 + 3) * UT_S + q] = v.w;
    }
    __syncthreads();

    // ---- s_u[q] = u[q,:] . w2  (conflict-free via u_t) ----
    if (tid < 64) {
        float acc = 0.f;
        #pragma unroll 8
        for (int k = 0; k < DN; k++) acc += u_t[k * UT_S + tid] * w_s[DN + k];
        s_u[tid] = acc;
    }

    const int ty = tid >> 4, tx = tid & 15;   // thread tile: rows 4*ty.., q 4*tx..
    const int row_a = tid >> 3;               // staging: rows row_a, row_a+32
    const int k4a   = (tid & 7) * 4;          // staging: 4 k's within chunk

    float c1[4][4];
    #pragma unroll
    for (int r = 0; r < 4; r++)
        #pragma unroll
        for (int j = 0; j < 4; j++) c1[r][j] = 0.f;

    float sh0 = 0.f, sh1 = 0.f;   // partial h.w1 for rows row_a, row_a+32

    // ---- stage chunk 0 (h*w3, transposed into A_t buf 0) ----
    {
        float4 pa0 = *(const float4*)(hrow + row_a * DN + k4a);
        float4 pa1 = *(const float4*)(hrow + (row_a + 32) * DN + k4a);
        sh0 += pa0.x * w_s[k4a + 0] + pa0.y * w_s[k4a + 1]
             + pa0.z * w_s[k4a + 2] + pa0.w * w_s[k4a + 3];
        sh1 += pa1.x * w_s[k4a + 0] + pa1.y * w_s[k4a + 1]
             + pa1.z * w_s[k4a + 2] + pa1.w * w_s[k4a + 3];
        const float* w3 = w_s + 2 * DN + k4a;
        float* At = A_t;  // buffer 0
        At[(k4a + 0) * ATR_S + row_a] = pa0.x * w3[0];
        At[(k4a + 1) * ATR_S + row_a] = pa0.y * w3[1];
        At[(k4a + 2) * ATR_S + row_a] = pa0.z * w3[2];
        At[(k4a + 3) * ATR_S + row_a] = pa0.w * w3[3];
        At[(k4a + 0) * ATR_S + row_a + 32] = pa1.x * w3[0];
        At[(k4a + 1) * ATR_S + row_a + 32] = pa1.y * w3[1];
        At[(k4a + 2) * ATR_S + row_a + 32] = pa1.z * w3[2];
        At[(k4a + 3) * ATR_S + row_a + 32] = pa1.w * w3[3];
    }
    __syncthreads();

    // ---- GEMM1 main loop: 8 k-chunks of 32, double-buffered (1 sync/chunk) ----
    for (int c = 0; c < 8; c++) {
        const int kc = c * 32;
        const float* Acur = A_t + (c & 1) * 32 * ATR_S;

        // stage chunk c+1 into the other buffer (overlaps with compute below)
        if (c < 7) {
            const int kn = kc + 32;
            float4 pa0 = *(const float4*)(hrow + row_a * DN + kn + k4a);
            float4 pa1 = *(const float4*)(hrow + (row_a + 32) * DN + kn + k4a);
            sh0 += pa0.x * w_s[kn + k4a + 0] + pa0.y * w_s[kn + k4a + 1]
                 + pa0.z * w_s[kn + k4a + 2] + pa0.w * w_s[kn + k4a + 3];
            sh1 += pa1.x * w_s[kn + k4a + 0] + pa1.y * w_s[kn + k4a + 1]
                 + pa1.z * w_s[kn + k4a + 2] + pa1.w * w_s[kn + k4a + 3];
            const float* w3 = w_s + 2 * DN + kn + k4a;
            float* An = A_t + ((c + 1) & 1) * 32 * ATR_S;
            An[(k4a + 0) * ATR_S + row_a] = pa0.x * w3[0];
            An[(k4a + 1) * ATR_S + row_a] = pa0.y * w3[1];
            An[(k4a + 2) * ATR_S + row_a] = pa0.z * w3[2];
            An[(k4a + 3) * ATR_S + row_a] = pa0.w * w3[3];
            An[(k4a + 0) * ATR_S + row_a + 32] = pa1.x * w3[0];
            An[(k4a + 1) * ATR_S + row_a + 32] = pa1.y * w3[1];
            An[(k4a + 2) * ATR_S + row_a + 32] = pa1.z * w3[2];
            An[(k4a + 3) * ATR_S + row_a + 32] = pa1.w * w3[3];
        }

        // register-tiled 4x4 FMA; BOTH operands contiguous LDS.128 (conflict-free)
        #pragma unroll 8
        for (int kk = 0; kk < 32; kk++) {
            float4 aa = *(const float4*)(Acur + kk * ATR_S + ty * 4);
            float4 bb = *(const float4*)(u_t + (kc + kk) * UT_S + tx * 4);
            c1[0][0] += aa.x * bb.x; c1[0][1] += aa.x * bb.y; c1[0][2] += aa.x * bb.z; c1[0][3] += aa.x * bb.w;
            c1[1][0] += aa.y * bb.x; c1[1][1] += aa.y * bb.y; c1[1][2] += aa.y * bb.z; c1[1][3] += aa.y * bb.w;
            c1[2][0] += aa.z * bb.x; c1[2][1] += aa.z * bb.y; c1[2][2] += aa.z * bb.z; c1[2][3] += aa.z * bb.w;
            c1[3][0] += aa.w * bb.x; c1[3][1] += aa.w * bb.y; c1[3][2] += aa.w * bb.z; c1[3][3] += aa.w * bb.w;
        }
        __syncthreads();
    }

    // ---- reduce s_h partials over the 8 lanes sharing a row ----
    #pragma unroll
    for (int o = 4; o >= 1; o >>= 1) {
        sh0 += __shfl_down_sync(0xffffffffu, sh0, o, 8);
        sh1 += __shfl_down_sync(0xffffffffu, sh1, o, 8);
    }
    if ((tid & 7) == 0) { s_h[row_a] = sh0; s_h[row_a + 32] = sh1; }
    __syncthreads();

    // ---- epilogue: softmax over q (s_h and bias cancel), write a_t + rowmax ----
    // NOTE: c1[r] holds row 4*ty+r, cols 4*tx..4*tx+3 (q). Here tile cols come
    // from u_t[.. + tx*4], rows from A_t[.. + ty*4] => row=4*ty+r is the j index.
    #pragma unroll
    for (int r = 0; r < 4; r++) {
        const int row = ty * 4 + r;
        float v0 = c1[r][0] + s_u[tx * 4 + 0];
        float v1 = c1[r][1] + s_u[tx * 4 + 1];
        float v2 = c1[r][2] + s_u[tx * 4 + 2];
        float v3 = c1[r][3] + s_u[tx * 4 + 3];
        float mx = fmaxf(fmaxf(v0, v1), fmaxf(v2, v3));
        #pragma unroll
        for (int o = 8; o >= 1; o >>= 1) mx = fmaxf(mx, __shfl_xor_sync(0xffffffffu, mx, o, 16));
        float e0 = __expf(v0 - mx), e1 = __expf(v1 - mx);
        float e2 = __expf(v2 - mx), e3 = __expf(v3 - mx);
        float sum = e0 + e1 + e2 + e3;
        #pragma unroll
        for (int o = 8; o >= 1; o >>= 1) sum += __shfl_xor_sync(0xffffffffu, sum, o, 16);
        float inv = 1.f / sum;
        a_t[(tx * 4 + 0) * AT_S + row] = e0 * inv;
        a_t[(tx * 4 + 1) * AT_S + row] = e1 * inv;
        a_t[(tx * 4 + 2) * AT_S + row] = e2 * inv;
        a_t[(tx * 4 + 3) * AT_S + row] = e3 * inv;
        if (tx == 0) g_rowmax[bm * JXN + j0 + row] = mx + s_h[row];
    }
    __syncthreads();

    // ---- GEMM2 (u_att) + write segments 0..2  (both operands conflict-free) ----
    const size_t outbase = (size_t)(bm * JXN + j0) * (4 * DN);
    for (int p = 0; p < 4; p++) {
        float c2[4][4];
        #pragma unroll
        for (int r = 0; r < 4; r++)
            #pragma unroll
            for (int j = 0; j < 4; j++) c2[r][j] = 0.f;
        #pragma unroll 8
        for (int k = 0; k < 64; k++) {
            float4 aa = *(const float4*)(a_t + k * AT_S + ty * 4);
            float4 bb = *(const float4*)(u_sm + k * USM_S + p * 64 + tx * 4);
            c2[0][0] += aa.x * bb.x; c2[0][1] += aa.x * bb.y; c2[0][2] += aa.x * bb.z; c2[0][3] += aa.x * bb.w;
            c2[1][0] += aa.y * bb.x; c2[1][1] += aa.y * bb.y; c2[1][2] += aa.y * bb.z; c2[1][3] += aa.y * bb.w;
            c2[2][0] += aa.z * bb.x; c2[2][1] += aa.z * bb.y; c2[2][2] += aa.z * bb.z; c2[2][3] += aa.z * bb.w;
            c2[3][0] += aa.w * bb.x; c2[3][1] += aa.w * bb.y; c2[3][2] += aa.w * bb.z; c2[3][3] += aa.w * bb.w;
        }
        #pragma unroll
        for (int r = 0; r < 4; r++) {
            const int row = ty * 4 + r;
            const int dg  = p * 64 + tx * 4;
            float4 h4 = *(const float4*)(hrow + row * DN + dg);   // L2-hot reload
            float4 ua = make_float4(c2[r][0], c2[r][1], c2[r][2], c2[r][3]);
            float4 hu = make_float4(h4.x * ua.x, h4.y * ua.y, h4.z * ua.z, h4.w * ua.w);
            float* ob = out + outbase + (size_t)row * (4 * DN);
            *(float4*)(ob + dg)           = h4;   // segment 0: h
            *(float4*)(ob + DN + dg)      = ua;   // segment 1: u_att
            *(float4*)(ob + 2 * DN + dg)  = hu;   // segment 2: h*u_att
        }
    }
}

// ---------------------------------------------------------------------------
// Kernel 2: per CTA = one (b,m, d-half). p = softmax_j(rowmax);
// h_att = sum_j p_j h_j; writes segment 3: h * h_att (broadcast over j).
// ---------------------------------------------------------------------------
__global__ void __launch_bounds__(256)
attn_k2(const float* __restrict__ hg, float* __restrict__ out)
{
    __shared__ float  p_s[JXN];
    __shared__ float4 part[8][32];

    const int bm  = blockIdx.x >> 1;
    const int dh  = (blockIdx.x & 1) * 128;
    const int tid = threadIdx.x;
    const float* __restrict__ hb = hg + (size_t)bm * JXN * DN;

    if (tid < 32) {
        float v0 = g_rowmax[bm * JXN + tid];
        float v1 = g_rowmax[bm * JXN + tid + 32];
        float v2 = g_rowmax[bm * JXN + tid + 64];
        float v3 = g_rowmax[bm * JXN + tid + 96];
        float mx = fmaxf(fmaxf(v0, v1), fmaxf(v2, v3));
        #pragma unroll
        for (int o = 16; o >= 1; o >>= 1) mx = fmaxf(mx, __shfl_xor_sync(0xffffffffu, mx, o));
        float e0 = __expf(v0 - mx), e1 = __expf(v1 - mx);
        float e2 = __expf(v2 - mx), e3 = __expf(v3 - mx);
        float s = e0 + e1 + e2 + e3;
        #pragma unroll
        for (int o = 16; o >= 1; o >>= 1) s += __shfl_xor_sync(0xffffffffu, s, o);
        float inv = 1.f / s;
        p_s[tid]      = e0 * inv;
        p_s[tid + 32] = e1 * inv;
        p_s[tid + 64] = e2 * inv;
        p_s[tid + 96] = e3 * inv;
    }
    __syncthreads();

    const int jg = tid >> 5, dq = tid & 31;   // 8 j-groups x 16 j; 32 float4 slots
    const int dof = dh + dq * 4;

    float4 acc = make_float4(0.f, 0.f, 0.f, 0.f);
    #pragma unroll 4
    for (int j = jg * 16; j < jg * 16 + 16; j++) {
        float4 hv = *(const float4*)(hb + j * DN + dof);
        float pj = p_s[j];
        acc.x += pj * hv.x; acc.y += pj * hv.y; acc.z += pj * hv.z; acc.w += pj * hv.w;
    }
    part[jg][dq] = acc;
    __syncthreads();
    if (tid < 32) {
        float4 s = part[0][tid];
        #pragma unroll
        for (int g = 1; g < 8; g++) {
            float4 v = part[g][tid];
            s.x += v.x; s.y += v.y; s.z += v.z; s.w += v.w;
        }
        part[0][tid] = s;
    }
    __syncthreads();
    const float4 ha = part[0][dq];
    #pragma unroll 2
    for (int j = jg * 16; j < jg * 16 + 16; j++) {
        float4 hv = *(const float4*)(hb + j * DN + dof);   // L1-hot second read
        float4 o;
        o.x = hv.x * ha.x; o.y = hv.y * ha.y; o.z = hv.z * ha.z; o.w = hv.w * ha.w;
        *(float4*)(out + (size_t)(bm * JXN + j) * (4 * DN) + 3 * DN + dof) = o;
    }
}

// ---------------------------------------------------------------------------
extern "C" void kernel_launch(void* const* d_in, const int* in_sizes, int n_in,
                              void* d_out, int out_size)
{
    (void)in_sizes; (void)n_in; (void)out_size;
    const float* h = (const float*)d_in[0];
    const float* u = (const float*)d_in[1];
    const float* w = (const float*)d_in[2];
    // d_in[3] is the scalar bias b: it cancels in both softmaxes -> unused.
    float* out = (float*)d_out;

    const size_t smem = SMEM_FLOATS * sizeof(float);  // ~166 KB
    cudaFuncSetAttribute(attn_k1, cudaFuncAttributeMaxDynamicSharedMemorySize, (int)smem);

    attn_k1<<<BB * MM * 2, 256, smem>>>(h, u, w, out);
    attn_k2<<<BB * MM * 2, 256>>>(h, out);
}

// round 6
// speedup vs baseline: 1.4970x; 1.4617x over previous
#include <cuda_runtime.h>
#include <cstdint>
#include <cstddef>

// Problem constants (fixed by the dataset)
#define BB 16
#define MM 16
#define JXN 128
#define JQN 64
#define DN 256

// shared memory layout strides (floats)
constexpr int UT_S  = 68;   // u_t  [256][68]  (u transposed: [d][q])
constexpr int USM_S = 260;  // u_sm [64][260]  (u row-major:  [q][d])
constexpr int AS_S  = 36;   // A_s  [128][36]  (h*w3 chunk, row-major, k-chunk=32)
constexpr int AT_S  = 132;  // a_t  [64][132]  (attention transposed [q][j])

// u_t + u_sm + A_s + a_t + w_s + s_u + s_h + s_pm + p_s + part
constexpr int SMEM_FLOATS = 256*UT_S + 64*USM_S + 128*AS_S + 64*AT_S
                          + 3*DN + 64 + 128 + 128 + 128 + 8*64*4;

// ---------------------------------------------------------------------------
// Fused kernel: per CTA = one (b,m), all 128 j rows. 512 threads.
//  - GEMM1: C[j,q] = sum_d (h[j,d]*w3[d]) * u[q,d]        (128x64x256)
//  - softmax over q of (C + s_u) -> a_t ; rowmax+s_h -> s_pm (smem)
//  - p = softmax_j(s_pm); GEMM2: u_att = a . u            (128x256x64)
//  - h_att[d] = sum_j p_j h[j,d]
//  - writes all 4 output segments.
// ---------------------------------------------------------------------------
__global__ void __launch_bounds__(512, 1)
attn_fused(const float* __restrict__ hg, const float* __restrict__ ug,
           const float* __restrict__ wg, float* __restrict__ out)
{
    extern __shared__ float sm[];
    float* u_t  = sm;                      // 256*68
    float* u_sm = u_t  + 256 * UT_S;       // 64*260
    float* A_s  = u_sm + 64  * USM_S;      // 128*36
    float* a_t  = A_s  + 128 * AS_S;       // 64*132
    float* w_s  = a_t  + 64  * AT_S;       // 768  (w1|w2|w3)
    float* s_u  = w_s  + 3 * DN;           // 64
    float* s_h  = s_u  + 64;               // 128
    float* s_pm = s_h  + 128;              // 128 (rowmax + s_h)
    float* p_s  = s_pm + 128;              // 128
    float4* part = (float4*)(p_s + 128);   // [8][64] float4 = 2048 floats

    const int tid = threadIdx.x;
    const int bm  = blockIdx.x;
    const int b   = bm >> 4;

    const float* __restrict__ hrow = hg + (size_t)bm * JXN * DN;
    const float* __restrict__ ub   = ug + (size_t)b * JQN * DN;

    // ---- load w into smem ----
    for (int i = tid; i < 3 * DN; i += 512) w_s[i] = wg[i];

    // ---- fill u_sm (row-major copy of u[b], coalesced) ----
    for (int idx = tid; idx < JQN * (DN / 4); idx += 512) {
        int q = idx >> 6, d4 = idx & 63;
        float4 v = *(const float4*)(ub + q * DN + d4 * 4);
        *(float4*)(u_sm + q * USM_S + d4 * 4) = v;
    }
    // ---- fill u_t (transposed [d][q]) ----
    for (int idx = tid; idx < (DN / 4) * JQN; idx += 512) {
        int d4 = idx >> 6, q = idx & 63;
        float4 v = *(const float4*)(ub + q * DN + d4 * 4);
        u_t[(d4 * 4 + 0) * UT_S + q] = v.x;
        u_t[(d4 * 4 + 1) * UT_S + q] = v.y;
        u_t[(d4 * 4 + 2) * UT_S + q] = v.z;
        u_t[(d4 * 4 + 3) * UT_S + q] = v.w;
    }
    __syncthreads();

    // ---- s_u[q] = u[q,:] . w2 ----
    if (tid < 64) {
        float acc = 0.f;
        #pragma unroll 8
        for (int k = 0; k < DN; k++) acc += u_t[k * UT_S + tid] * w_s[DN + k];
        s_u[tid] = acc;
    }

    const int ty = tid >> 4, tx = tid & 15;   // tile: j rows 4*ty.. (0..127), q 4*tx..
    const int row_a = tid >> 2;               // staging: row 0..127
    const int k8a   = (tid & 3) * 8;          // staging: 8 k's within chunk

    float c1[4][4];
    #pragma unroll
    for (int r = 0; r < 4; r++)
        #pragma unroll
        for (int j = 0; j < 4; j++) c1[r][j] = 0.f;

    float shp = 0.f;   // partial h.w1 for row row_a

    // prefetch chunk 0 (2 float4 per thread)
    float4 pa0 = *(const float4*)(hrow + row_a * DN + k8a);
    float4 pa1 = *(const float4*)(hrow + row_a * DN + k8a + 4);

    // ---- GEMM1 main loop: 8 k-chunks of 32 ----
    for (int c = 0; c < 8; c++) {
        const int kc = c * 32;
        // s_h partial (w1) from raw h
        shp += pa0.x * w_s[kc + k8a + 0] + pa0.y * w_s[kc + k8a + 1]
             + pa0.z * w_s[kc + k8a + 2] + pa0.w * w_s[kc + k8a + 3]
             + pa1.x * w_s[kc + k8a + 4] + pa1.y * w_s[kc + k8a + 5]
             + pa1.z * w_s[kc + k8a + 6] + pa1.w * w_s[kc + k8a + 7];
        // scale by w3, stage to A_s (row-major)
        const float* w3 = w_s + 2 * DN + kc + k8a;
        float4 t0, t1;
        t0.x = pa0.x * w3[0]; t0.y = pa0.y * w3[1]; t0.z = pa0.z * w3[2]; t0.w = pa0.w * w3[3];
        t1.x = pa1.x * w3[4]; t1.y = pa1.y * w3[5]; t1.z = pa1.z * w3[6]; t1.w = pa1.w * w3[7];
        *(float4*)(A_s + row_a * AS_S + k8a)     = t0;
        *(float4*)(A_s + row_a * AS_S + k8a + 4) = t1;
        __syncthreads();
        // prefetch next chunk
        if (c < 7) {
            pa0 = *(const float4*)(hrow + row_a * DN + kc + 32 + k8a);
            pa1 = *(const float4*)(hrow + row_a * DN + kc + 32 + k8a + 4);
        }
        // register-tiled 4x4 FMA over this k-chunk
        #pragma unroll 8
        for (int kk = 0; kk < 32; kk++) {
            float a0 = A_s[(ty * 4 + 0) * AS_S + kk];
            float a1 = A_s[(ty * 4 + 1) * AS_S + kk];
            float a2 = A_s[(ty * 4 + 2) * AS_S + kk];
            float a3 = A_s[(ty * 4 + 3) * AS_S + kk];
            float4 bb = *(const float4*)(u_t + (kc + kk) * UT_S + tx * 4);
            c1[0][0] += a0 * bb.x; c1[0][1] += a0 * bb.y; c1[0][2] += a0 * bb.z; c1[0][3] += a0 * bb.w;
            c1[1][0] += a1 * bb.x; c1[1][1] += a1 * bb.y; c1[1][2] += a1 * bb.z; c1[1][3] += a1 * bb.w;
            c1[2][0] += a2 * bb.x; c1[2][1] += a2 * bb.y; c1[2][2] += a2 * bb.z; c1[2][3] += a2 * bb.w;
            c1[3][0] += a3 * bb.x; c1[3][1] += a3 * bb.y; c1[3][2] += a3 * bb.z; c1[3][3] += a3 * bb.w;
        }
        __syncthreads();
    }

    // ---- reduce s_h partial over 4 lanes sharing a row ----
    shp += __shfl_down_sync(0xffffffffu, shp, 2, 4);
    shp += __shfl_down_sync(0xffffffffu, shp, 1, 4);
    if ((tid & 3) == 0) s_h[row_a] = shp;
    __syncthreads();

    // ---- softmax over q (s_h & bias cancel); write a_t + s_pm ----
    #pragma unroll
    for (int r = 0; r < 4; r++) {
        const int row = ty * 4 + r;
        float v0 = c1[r][0] + s_u[tx * 4 + 0];
        float v1 = c1[r][1] + s_u[tx * 4 + 1];
        float v2 = c1[r][2] + s_u[tx * 4 + 2];
        float v3 = c1[r][3] + s_u[tx * 4 + 3];
        float mx = fmaxf(fmaxf(v0, v1), fmaxf(v2, v3));
        #pragma unroll
        for (int o = 8; o >= 1; o >>= 1) mx = fmaxf(mx, __shfl_xor_sync(0xffffffffu, mx, o, 16));
        float e0 = __expf(v0 - mx), e1 = __expf(v1 - mx);
        float e2 = __expf(v2 - mx), e3 = __expf(v3 - mx);
        float sum = e0 + e1 + e2 + e3;
        #pragma unroll
        for (int o = 8; o >= 1; o >>= 1) sum += __shfl_xor_sync(0xffffffffu, sum, o, 16);
        float inv = 1.f / sum;
        a_t[(tx * 4 + 0) * AT_S + row] = e0 * inv;
        a_t[(tx * 4 + 1) * AT_S + row] = e1 * inv;
        a_t[(tx * 4 + 2) * AT_S + row] = e2 * inv;
        a_t[(tx * 4 + 3) * AT_S + row] = e3 * inv;
        if (tx == 0) s_pm[row] = mx + s_h[row];
    }
    __syncthreads();

    // ---- p = softmax_j(s_pm), one warp ----
    if (tid < 32) {
        float v0 = s_pm[tid], v1 = s_pm[tid + 32], v2 = s_pm[tid + 64], v3 = s_pm[tid + 96];
        float mx = fmaxf(fmaxf(v0, v1), fmaxf(v2, v3));
        #pragma unroll
        for (int o = 16; o >= 1; o >>= 1) mx = fmaxf(mx, __shfl_xor_sync(0xffffffffu, mx, o));
        float e0 = __expf(v0 - mx), e1 = __expf(v1 - mx);
        float e2 = __expf(v2 - mx), e3 = __expf(v3 - mx);
        float s = e0 + e1 + e2 + e3;
        #pragma unroll
        for (int o = 16; o >= 1; o >>= 1) s += __shfl_xor_sync(0xffffffffu, s, o);
        float inv = 1.f / s;
        p_s[tid]      = e0 * inv;
        p_s[tid + 32] = e1 * inv;
        p_s[tid + 64] = e2 * inv;
        p_s[tid + 96] = e3 * inv;
    }
    __syncthreads();

    // ---- GEMM2 (u_att) + write segments 0..2 ----
    const size_t outbase = (size_t)bm * JXN * (4 * DN);
    for (int p = 0; p < 4; p++) {
        float c2[4][4];
        #pragma unroll
        for (int r = 0; r < 4; r++)
            #pragma unroll
            for (int j = 0; j < 4; j++) c2[r][j] = 0.f;
        #pragma unroll 8
        for (int k = 0; k < 64; k++) {
            float4 aa = *(const float4*)(a_t + k * AT_S + ty * 4);
            float4 bb = *(const float4*)(u_sm + k * USM_S + p * 64 + tx * 4);
            c2[0][0] += aa.x * bb.x; c2[0][1] += aa.x * bb.y; c2[0][2] += aa.x * bb.z; c2[0][3] += aa.x * bb.w;
            c2[1][0] += aa.y * bb.x; c2[1][1] += aa.y * bb.y; c2[1][2] += aa.y * bb.z; c2[1][3] += aa.y * bb.w;
            c2[2][0] += aa.z * bb.x; c2[2][1] += aa.z * bb.y; c2[2][2] += aa.z * bb.z; c2[2][3] += aa.z * bb.w;
            c2[3][0] += aa.w * bb.x; c2[3][1] += aa.w * bb.y; c2[3][2] += aa.w * bb.z; c2[3][3] += aa.w * bb.w;
        }
        #pragma unroll
        for (int r = 0; r < 4; r++) {
            const int row = ty * 4 + r;
            const int dg  = p * 64 + tx * 4;
            float4 h4 = *(const float4*)(hrow + row * DN + dg);   // L2-hot reload
            float4 ua = make_float4(c2[r][0], c2[r][1], c2[r][2], c2[r][3]);
            float4 hu = make_float4(h4.x * ua.x, h4.y * ua.y, h4.z * ua.z, h4.w * ua.w);
            float* ob = out + outbase + (size_t)row * (4 * DN);
            *(float4*)(ob + dg)           = h4;   // segment 0: h
            *(float4*)(ob + DN + dg)      = ua;   // segment 1: u_att
            *(float4*)(ob + 2 * DN + dg)  = hu;   // segment 2: h*u_att
        }
    }
    __syncthreads();

    // ---- h_att = sum_j p_j h[j,:]; write segment 3 ----
    {
        const int jg = tid >> 6, dq = tid & 63;   // 8 j-groups x 16 j; 64 float4 d-slots
        float4 acc = make_float4(0.f, 0.f, 0.f, 0.f);
        #pragma unroll 4
        for (int j = jg * 16; j < jg * 16 + 16; j++) {
            float4 hv = *(const float4*)(hrow + j * DN + dq * 4);
            float pj = p_s[j];
            acc.x += pj * hv.x; acc.y += pj * hv.y; acc.z += pj * hv.z; acc.w += pj * hv.w;
        }
        part[jg * 64 + dq] = acc;
        __syncthreads();
        if (tid < 64) {
            float4 s = part[tid];
            #pragma unroll
            for (int g = 1; g < 8; g++) {
                float4 v = part[g * 64 + tid];
                s.x += v.x; s.y += v.y; s.z += v.z; s.w += v.w;
            }
            part[tid] = s;
        }
        __syncthreads();
        const float4 ha = part[dq];
        #pragma unroll 2
        for (int j = jg * 16; j < jg * 16 + 16; j++) {
            float4 hv = *(const float4*)(hrow + j * DN + dq * 4);   // L1-hot re-read
            float4 o;
            o.x = hv.x * ha.x; o.y = hv.y * ha.y; o.z = hv.z * ha.z; o.w = hv.w * ha.w;
            *(float4*)(out + outbase + (size_t)j * (4 * DN) + 3 * DN + dq * 4) = o;
        }
    }
}

// ---------------------------------------------------------------------------
extern "C" void kernel_launch(void* const* d_in, const int* in_sizes, int n_in,
                              void* d_out, int out_size)
{
    (void)in_sizes; (void)n_in; (void)out_size;
    const float* h = (const float*)d_in[0];
    const float* u = (const float*)d_in[1];
    const float* w = (const float*)d_in[2];
    // d_in[3] is the scalar bias b: it cancels in both softmaxes -> unused.
    float* out = (float*)d_out;

    const size_t smem = SMEM_FLOATS * sizeof(float);  // ~202 KB
    cudaFuncSetAttribute(attn_fused, cudaFuncAttributeMaxDynamicSharedMemorySize, (int)smem);

    attn_fused<<<BB * MM, 512, smem>>>(h, u, w, out);
}

// round 8
// speedup vs baseline: 1.6091x; 1.0749x over previous
#include <cuda_runtime.h>
#include <cstdint>
#include <cstddef>

#define BB 16
#define MM 16
#define JXN 128
#define JQN 64
#define DN 256

// ---------------- smem layout (float indices) --------------------------------
// sp   [128][68]  : GEMM1 C1, then (in-place) P (tf32), A of GEMM2
// D2   [128][68]  : GEMM2 output slab bounce buffer
// w    [768], s_u[64], s_h[128], s_pm[128], p_s[128], part[8*64 float4]
// PH region (phase-overlapped):
//   phase1: u_qd [64][260] tf32 (B of GEMM1) + A_s [128][68] tf32 (A chunks)
//   phase2: u_dq [256][68] tf32 (B of GEMM2)
constexpr int OFF_SP   = 0;
constexpr int OFF_D2   = 8704;
constexpr int OFF_W    = 17408;
constexpr int OFF_SU   = 18176;
constexpr int OFF_SH   = 18240;
constexpr int OFF_SPM  = 18368;
constexpr int OFF_PS   = 18496;
constexpr int OFF_PART = 18624;   // 2048 floats
constexpr int OFF_PH   = 20672;
constexpr int OFF_UQD  = OFF_PH;            // 64*260 = 16640
constexpr int OFF_AS   = OFF_PH + 16640;    // 128*68 = 8704
constexpr int OFF_UDQ  = OFF_PH;            // 256*68 = 17408 (fits in 16640+8704)
constexpr int SMEM_FLOATS = OFF_PH + 16640 + 8704;   // 46016 -> 184064 B

__device__ __forceinline__ uint32_t f2t(float x) {   // fp32 -> tf32 (round-nearest)
    uint32_t r;
    asm("cvt.rna.tf32.f32 %0, %1;" : "=r"(r) : "f"(x));
    return r;
}
__device__ __forceinline__ float f2tf(float x) { return __uint_as_float(f2t(x)); }

// m16n8k8 tf32 mma (base sm_80+ ISA; valid on compute_103)
#define MMA_TF32(c, a, b)                                                       \
    asm volatile(                                                               \
        "mma.sync.aligned.m16n8k8.row.col.f32.tf32.tf32.f32 "                   \
        "{%0,%1,%2,%3}, {%4,%5,%6,%7}, {%8,%9}, {%0,%1,%2,%3};"                 \
        : "+f"((c)[0]), "+f"((c)[1]), "+f"((c)[2]), "+f"((c)[3])                \
        : "r"((a)[0]), "r"((a)[1]), "r"((a)[2]), "r"((a)[3]),                   \
          "r"((b)[0]), "r"((b)[1]))

// ---------------------------------------------------------------------------
// Fused kernel, CTA = one (b,m). 512 threads, tensor cores via mma.sync.
// ---------------------------------------------------------------------------
__global__ void __launch_bounds__(512, 1)
attn_mma(const float* __restrict__ hg, const float* __restrict__ ug,
         const float* __restrict__ wg, float* __restrict__ out)
{
    extern __shared__ float smf[];
    float*  sp   = smf + OFF_SP;
    float*  D2   = smf + OFF_D2;
    float*  wsm  = smf + OFF_W;
    float*  s_u  = smf + OFF_SU;
    float*  s_h  = smf + OFF_SH;
    float*  s_pm = smf + OFF_SPM;
    float*  p_s  = smf + OFF_PS;
    float4* part = (float4*)(smf + OFF_PART);
    float*  u_qd = smf + OFF_UQD;
    float*  A_s  = smf + OFF_AS;
    float*  u_dq = smf + OFF_UDQ;

    const int tid  = threadIdx.x;
    const int wid  = tid >> 5;
    const int lane = tid & 31;
    const int g    = lane >> 2;     // mma group id
    const int t    = lane & 3;      // thread-in-group
    const int bm   = blockIdx.x;
    const int b    = bm >> 4;

    const float* __restrict__ hrow = hg + (size_t)bm * JXN * DN;
    const float* __restrict__ ub   = ug + (size_t)b * JQN * DN;
    const size_t outbase = (size_t)bm * JXN * (4 * DN);

    // ---- stage w; stage u_qd (tf32, [q][d], stride 260) ----
    for (int i = tid; i < 3 * DN; i += 512) wsm[i] = wg[i];
    for (int idx = tid; idx < 64 * 64; idx += 512) {
        int q = idx >> 6, d4 = idx & 63;
        float4 v = *(const float4*)(ub + q * DN + d4 * 4);
        float* p = u_qd + q * 260 + d4 * 4;
        p[0] = f2tf(v.x); p[1] = f2tf(v.y); p[2] = f2tf(v.z); p[3] = f2tf(v.w);
    }
    // ---- s_u[q] = u[q,:] . w2 (fp32 from gmem; 4 lanes per q) ----
    if (tid < 256) {
        int q = tid >> 2, sg = tid & 3;
        const float* up  = ub + q * DN + sg * 64;
        const float* w2p = wg + DN + sg * 64;
        float acc = 0.f;
        #pragma unroll 16
        for (int i = 0; i < 16; i++) {
            float4 a = *(const float4*)(up + 4 * i);
            float4 w = *(const float4*)(w2p + 4 * i);
            acc += a.x * w.x + a.y * w.y + a.z * w.z + a.w * w.w;
        }
        acc += __shfl_xor_sync(0xffffffffu, acc, 1, 4);
        acc += __shfl_xor_sync(0xffffffffu, acc, 2, 4);
        if (sg == 0) s_u[q] = acc;
    }
    __syncthreads();

    // ---- GEMM1: C1[128 j][64 q] = (h*w3) . u^T, K=256 in 4 chunks of 64 ----
    const int wj = wid & 3;     // j-tile group: rows wj*32..+32
    const int wq = wid >> 2;    // q-tile group: cols wq*16..+16
    const int srow = tid >> 2, soff = (tid & 3) * 16;   // staging/softmax mapping

    float c1f[2][2][4];
    #pragma unroll
    for (int mt = 0; mt < 2; mt++)
        #pragma unroll
        for (int nt = 0; nt < 2; nt++)
            #pragma unroll
            for (int i = 0; i < 4; i++) c1f[mt][nt][i] = 0.f;

    float shp = 0.f;
    for (int c = 0; c < 4; c++) {
        // stage A chunk (h*w3 tf32) + s_h partial
        #pragma unroll
        for (int i = 0; i < 4; i++) {
            const int dd = c * 64 + soff + 4 * i;
            float4 x = *(const float4*)(hrow + srow * DN + dd);
            const float* w1p = wsm + dd;
            shp += x.x * w1p[0] + x.y * w1p[1] + x.z * w1p[2] + x.w * w1p[3];
            const float* w3p = wsm + 2 * DN + dd;
            float* ap = A_s + srow * 68 + soff + 4 * i;
            ap[0] = f2tf(x.x * w3p[0]); ap[1] = f2tf(x.y * w3p[1]);
            ap[2] = f2tf(x.z * w3p[2]); ap[3] = f2tf(x.w * w3p[3]);
        }
        __syncthreads();
        #pragma unroll
        for (int it = 0; it < 8; it++) {
            const int kb = it * 8;
            uint32_t af[2][4], bf[2][2];
            #pragma unroll
            for (int mt = 0; mt < 2; mt++) {
                const float* ap = A_s + (wj * 32 + mt * 16 + g) * 68 + kb + t;
                af[mt][0] = __float_as_uint(ap[0]);
                af[mt][1] = __float_as_uint(ap[8 * 68]);
                af[mt][2] = __float_as_uint(ap[4]);
                af[mt][3] = __float_as_uint(ap[8 * 68 + 4]);
            }
            #pragma unroll
            for (int nt = 0; nt < 2; nt++) {
                const float* bp = u_qd + (wq * 16 + nt * 8 + g) * 260 + c * 64 + kb + t;
                bf[nt][0] = __float_as_uint(bp[0]);
                bf[nt][1] = __float_as_uint(bp[4]);
            }
            #pragma unroll
            for (int mt = 0; mt < 2; mt++)
                #pragma unroll
                for (int nt = 0; nt < 2; nt++)
                    MMA_TF32(c1f[mt][nt], af[mt], bf[nt]);
        }
        __syncthreads();
    }

    // ---- s_h ----
    shp += __shfl_xor_sync(0xffffffffu, shp, 1, 4);
    shp += __shfl_xor_sync(0xffffffffu, shp, 2, 4);
    if ((tid & 3) == 0) s_h[srow] = shp;

    // ---- store C1 fragments -> sp ----
    #pragma unroll
    for (int mt = 0; mt < 2; mt++)
        #pragma unroll
        for (int nt = 0; nt < 2; nt++) {
            float* cp = sp + (wj * 32 + mt * 16 + g) * 68 + wq * 16 + nt * 8 + 2 * t;
            *(float2*)cp            = make_float2(c1f[mt][nt][0], c1f[mt][nt][1]);
            *(float2*)(cp + 8 * 68) = make_float2(c1f[mt][nt][2], c1f[mt][nt][3]);
        }
    __syncthreads();

    // ---- softmax over q, in place (thread: row srow, 16 q at soff) ----
    {
        float v[16];
        #pragma unroll
        for (int i = 0; i < 16; i++) v[i] = sp[srow * 68 + soff + i] + s_u[soff + i];
        float mx = v[0];
        #pragma unroll
        for (int i = 1; i < 16; i++) mx = fmaxf(mx, v[i]);
        mx = fmaxf(mx, __shfl_xor_sync(0xffffffffu, mx, 1, 4));
        mx = fmaxf(mx, __shfl_xor_sync(0xffffffffu, mx, 2, 4));
        float sum = 0.f;
        #pragma unroll
        for (int i = 0; i < 16; i++) { v[i] = __expf(v[i] - mx); sum += v[i]; }
        sum += __shfl_xor_sync(0xffffffffu, sum, 1, 4);
        sum += __shfl_xor_sync(0xffffffffu, sum, 2, 4);
        float inv = 1.f / sum;
        #pragma unroll
        for (int i = 0; i < 16; i++) sp[srow * 68 + soff + i] = f2tf(v[i] * inv);
        if ((tid & 3) == 0) s_pm[srow] = mx + s_h[srow];
    }
    __syncthreads();

    // ---- stage u_dq (tf32, [d][q], stride 68) over freed phase1 region ----
    for (int idx = tid; idx < 64 * 64; idx += 512) {
        int q = idx & 63, d4 = idx >> 6;
        float4 v = *(const float4*)(ub + q * DN + d4 * 4);
        u_dq[(d4 * 4 + 0) * 68 + q] = f2tf(v.x);
        u_dq[(d4 * 4 + 1) * 68 + q] = f2tf(v.y);
        u_dq[(d4 * 4 + 2) * 68 + q] = f2tf(v.z);
        u_dq[(d4 * 4 + 3) * 68 + q] = f2tf(v.w);
    }
    __syncthreads();

    // ---- p = softmax_j(s_pm) (warp 0) ----
    if (wid == 0) {
        float v0 = s_pm[lane], v1 = s_pm[lane + 32], v2 = s_pm[lane + 64], v3 = s_pm[lane + 96];
        float mx = fmaxf(fmaxf(v0, v1), fmaxf(v2, v3));
        #pragma unroll
        for (int o = 16; o >= 1; o >>= 1) mx = fmaxf(mx, __shfl_xor_sync(0xffffffffu, mx, o));
        float e0 = __expf(v0 - mx), e1 = __expf(v1 - mx);
        float e2 = __expf(v2 - mx), e3 = __expf(v3 - mx);
        float s = e0 + e1 + e2 + e3;
        #pragma unroll
        for (int o = 16; o >= 1; o >>= 1) s += __shfl_xor_sync(0xffffffffu, s, o);
        float inv = 1.f / s;
        p_s[lane] = e0 * inv; p_s[lane + 32] = e1 * inv;
        p_s[lane + 64] = e2 * inv; p_s[lane + 96] = e3 * inv;
    }
    __syncthreads();

    // ---- GEMM2: u_att[128 j][256 d] = P . u, K=64, in 4 d-slabs of 64 ----
    for (int s = 0; s < 4; s++) {
        float d2f[2][2][4];
        #pragma unroll
        for (int mt = 0; mt < 2; mt++)
            #pragma unroll
            for (int nt = 0; nt < 2; nt++)
                #pragma unroll
                for (int i = 0; i < 4; i++) d2f[mt][nt][i] = 0.f;

        #pragma unroll
        for (int it = 0; it < 8; it++) {
            const int kb = it * 8;
            uint32_t af[2][4], bf[2][2];
            #pragma unroll
            for (int mt = 0; mt < 2; mt++) {
                const float* ap = sp + (wj * 32 + mt * 16 + g) * 68 + kb + t;
                af[mt][0] = __float_as_uint(ap[0]);
                af[mt][1] = __float_as_uint(ap[8 * 68]);
                af[mt][2] = __float_as_uint(ap[4]);
                af[mt][3] = __float_as_uint(ap[8 * 68 + 4]);
            }
            #pragma unroll
            for (int nt = 0; nt < 2; nt++) {
                const float* bp = u_dq + (s * 64 + wq * 16 + nt * 8 + g) * 68 + kb + t;
                bf[nt][0] = __float_as_uint(bp[0]);
                bf[nt][1] = __float_as_uint(bp[4]);
            }
            #pragma unroll
            for (int mt = 0; mt < 2; mt++)
                #pragma unroll
                for (int nt = 0; nt < 2; nt++)
                    MMA_TF32(d2f[mt][nt], af[mt], bf[nt]);
        }
        // fragments -> D2 bounce buffer
        #pragma unroll
        for (int mt = 0; mt < 2; mt++)
            #pragma unroll
            for (int nt = 0; nt < 2; nt++) {
                float* cp = D2 + (wj * 32 + mt * 16 + g) * 68 + wq * 16 + nt * 8 + 2 * t;
                *(float2*)cp            = make_float2(d2f[mt][nt][0], d2f[mt][nt][1]);
                *(float2*)(cp + 8 * 68) = make_float2(d2f[mt][nt][2], d2f[mt][nt][3]);
            }
        __syncthreads();
        // coalesced epilogue for this d-slab: segments 0,1,2
        {
            float* ob = out + outbase + (size_t)srow * (4 * DN);
            #pragma unroll
            for (int i = 0; i < 4; i++) {
                const int dl = soff + 4 * i;          // 0..63 within slab
                const int dgl = s * 64 + dl;          // global d
                float4 ua = make_float4(D2[srow * 68 + dl + 0], D2[srow * 68 + dl + 1],
                                        D2[srow * 68 + dl + 2], D2[srow * 68 + dl + 3]);
                float4 h4 = *(const float4*)(hrow + srow * DN + dgl);
                float4 hu = make_float4(h4.x * ua.x, h4.y * ua.y, h4.z * ua.z, h4.w * ua.w);
                *(float4*)(ob + dgl)            = h4;   // segment 0: h
                *(float4*)(ob + DN + dgl)       = ua;   // segment 1: u_att
                *(float4*)(ob + 2 * DN + dgl)   = hu;   // segment 2: h*u_att
            }
        }
        __syncthreads();
    }

    // ---- h_att = sum_j p_j h[j,:]; write segment 3 ----
    {
        const int jg = tid >> 6, dq = tid & 63;
        float4 acc = make_float4(0.f, 0.f, 0.f, 0.f);
        #pragma unroll 4
        for (int j = jg * 16; j < jg * 16 + 16; j++) {
            float4 hv = *(const float4*)(hrow + j * DN + dq * 4);
            float pj = p_s[j];
            acc.x += pj * hv.x; acc.y += pj * hv.y; acc.z += pj * hv.z; acc.w += pj * hv.w;
        }
        part[jg * 64 + dq] = acc;
        __syncthreads();
        if (tid < 64) {
            float4 sacc = part[tid];
            #pragma unroll
            for (int gg = 1; gg < 8; gg++) {
                float4 v = part[gg * 64 + tid];
                sacc.x += v.x; sacc.y += v.y; sacc.z += v.z; sacc.w += v.w;
            }
            part[tid] = sacc;
        }
        __syncthreads();
        const float4 ha = part[dq];
        #pragma unroll 2
        for (int j = jg * 16; j < jg * 16 + 16; j++) {
            float4 hv = *(const float4*)(hrow + j * DN + dq * 4);
            float4 o;
            o.x = hv.x * ha.x; o.y = hv.y * ha.y; o.z = hv.z * ha.z; o.w = hv.w * ha.w;
            *(float4*)(out + outbase + (size_t)j * (4 * DN) + 3 * DN + dq * 4) = o;
        }
    }
}

// ---------------------------------------------------------------------------
extern "C" void kernel_launch(void* const* d_in, const int* in_sizes, int n_in,
                              void* d_out, int out_size)
{
    (void)in_sizes; (void)n_in; (void)out_size;
    const float* h = (const float*)d_in[0];
    const float* u = (const float*)d_in[1];
    const float* w = (const float*)d_in[2];
    // d_in[3] (scalar bias b) cancels in both softmaxes -> unused.
    float* out = (float*)d_out;

    const size_t smem = SMEM_FLOATS * sizeof(float);   // 184064 B
    cudaFuncSetAttribute(attn_mma, cudaFuncAttributeMaxDynamicSharedMemorySize, (int)smem);
    attn_mma<<<BB * MM, 512, smem>>>(h, u, w, out);
}

// round 9
// speedup vs baseline: 1.6764x; 1.0418x over previous
#include <cuda_runtime.h>
#include <cstdint>
#include <cstddef>

#define BB 16
#define MM 16
#define JXN 128
#define JQN 64
#define DN 256

// ---------------- smem layout (float indices) --------------------------------
constexpr int OFF_SP   = 0;       // sp [128][68]: C1, then P (tf32) = A of GEMM2
constexpr int OFF_D2   = 8704;    // D2 [128][68]: GEMM2 slab bounce
constexpr int OFF_W    = 17408;   // w1|w2|w3 (768)
constexpr int OFF_SU   = 18176;   // s_u[64]
constexpr int OFF_SH   = 18240;   // s_h[128]
constexpr int OFF_SPM  = 18368;   // s_pm[128]
constexpr int OFF_PS   = 18496;   // p_s[128]
constexpr int OFF_PART = 18624;   // part: 8*64 float4 = 2048 floats
constexpr int OFF_UQD  = 20672;   // u_qd [64 q][260] tf32 (B of both GEMMs)
constexpr int OFF_AS   = 37312;   // A_s: 2 x [128][68] tf32 (double-buffered chunks)
constexpr int SMEM_FLOATS = 54720;   // 218,880 B

__device__ __forceinline__ uint32_t f2t(float x) {   // fp32 -> tf32 (round-nearest)
    uint32_t r;
    asm("cvt.rna.tf32.f32 %0, %1;" : "=r"(r) : "f"(x));
    return r;
}
__device__ __forceinline__ float f2tf(float x) { return __uint_as_float(f2t(x)); }

// m16n8k8 tf32 mma (base sm_80+ ISA; valid on compute_103)
#define MMA_TF32(c, a, b)                                                       \
    asm volatile(                                                               \
        "mma.sync.aligned.m16n8k8.row.col.f32.tf32.tf32.f32 "                   \
        "{%0,%1,%2,%3}, {%4,%5,%6,%7}, {%8,%9}, {%0,%1,%2,%3};"                 \
        : "+f"((c)[0]), "+f"((c)[1]), "+f"((c)[2]), "+f"((c)[3])                \
        : "r"((a)[0]), "r"((a)[1]), "r"((a)[2]), "r"((a)[3]),                   \
          "r"((b)[0]), "r"((b)[1]))

// ---------------------------------------------------------------------------
// Fused kernel, CTA = one (b,m). 512 threads, mma.sync tf32, latency-hidden.
// ---------------------------------------------------------------------------
__global__ void __launch_bounds__(512, 1)
attn_mma(const float* __restrict__ hg, const float* __restrict__ ug,
         const float* __restrict__ wg, float* __restrict__ out)
{
    extern __shared__ float smf[];
    float*  sp   = smf + OFF_SP;
    float*  D2   = smf + OFF_D2;
    float*  wsm  = smf + OFF_W;
    float*  s_u  = smf + OFF_SU;
    float*  s_h  = smf + OFF_SH;
    float*  s_pm = smf + OFF_SPM;
    float*  p_s  = smf + OFF_PS;
    float4* part = (float4*)(smf + OFF_PART);
    float*  u_qd = smf + OFF_UQD;
    float*  A_s  = smf + OFF_AS;

    const int tid  = threadIdx.x;
    const int wid  = tid >> 5;
    const int lane = tid & 31;
    const int g    = lane >> 2;     // mma group id
    const int t    = lane & 3;      // thread-in-group
    const int bm   = blockIdx.x;
    const int b    = bm >> 4;

    const float* __restrict__ hrow = hg + (size_t)bm * JXN * DN;
    const float* __restrict__ ub   = ug + (size_t)b * JQN * DN;
    const size_t outbase = (size_t)bm * JXN * (4 * DN);

    const int wj = wid & 3;                              // j-tile group
    const int wq = wid >> 2;                             // q/n-tile group
    const int srow = tid >> 2, soff = (tid & 3) * 16;    // staging/softmax mapping

    // ---- early prefetch of GEMM1 chunk 0 (hides behind u staging) ----
    float4 ph[4];
    #pragma unroll
    for (int i = 0; i < 4; i++)
        ph[i] = *(const float4*)(hrow + srow * DN + soff + 4 * i);

    // ---- stage w; stage u_qd (tf32, [q][d], stride 260) ----
    for (int i = tid; i < 3 * DN; i += 512) wsm[i] = wg[i];
    for (int idx = tid; idx < 64 * 64; idx += 512) {
        int q = idx >> 6, d4 = idx & 63;
        float4 v = *(const float4*)(ub + q * DN + d4 * 4);
        float* p = u_qd + q * 260 + d4 * 4;
        p[0] = f2tf(v.x); p[1] = f2tf(v.y); p[2] = f2tf(v.z); p[3] = f2tf(v.w);
    }
    // ---- s_u[q] = u[q,:] . w2 (fp32 from gmem; 4 lanes per q) ----
    if (tid < 256) {
        int q = tid >> 2, sg = tid & 3;
        const float* up  = ub + q * DN + sg * 64;
        const float* w2p = wg + DN + sg * 64;
        float acc = 0.f;
        #pragma unroll 16
        for (int i = 0; i < 16; i++) {
            float4 a = *(const float4*)(up + 4 * i);
            float4 w = *(const float4*)(w2p + 4 * i);
            acc += a.x * w.x + a.y * w.y + a.z * w.z + a.w * w.w;
        }
        acc += __shfl_xor_sync(0xffffffffu, acc, 1, 4);
        acc += __shfl_xor_sync(0xffffffffu, acc, 2, 4);
        if (sg == 0) s_u[q] = acc;
    }
    __syncthreads();

    // ---- GEMM1: C1[128 j][64 q] = (h*w3).u^T, K=256, 4 chunks, dbl-buffered --
    float c1f[2][2][4];
    #pragma unroll
    for (int mt = 0; mt < 2; mt++)
        #pragma unroll
        for (int nt = 0; nt < 2; nt++)
            #pragma unroll
            for (int i = 0; i < 4; i++) c1f[mt][nt][i] = 0.f;

    float shp = 0.f;
    for (int c = 0; c < 4; c++) {
        float* Ab = A_s + (c & 1) * 8704;
        // s_h partial + tf32 scale/stage from prefetched regs
        #pragma unroll
        for (int i = 0; i < 4; i++) {
            const int dd = c * 64 + soff + 4 * i;
            float4 x = ph[i];
            const float* w1p = wsm + dd;
            shp += x.x * w1p[0] + x.y * w1p[1] + x.z * w1p[2] + x.w * w1p[3];
            const float* w3p = wsm + 2 * DN + dd;
            float* ap = Ab + srow * 68 + soff + 4 * i;
            ap[0] = f2tf(x.x * w3p[0]); ap[1] = f2tf(x.y * w3p[1]);
            ap[2] = f2tf(x.z * w3p[2]); ap[3] = f2tf(x.w * w3p[3]);
        }
        __syncthreads();
        // prefetch next chunk while MMAing this one
        if (c < 3) {
            #pragma unroll
            for (int i = 0; i < 4; i++)
                ph[i] = *(const float4*)(hrow + srow * DN + (c + 1) * 64 + soff + 4 * i);
        }
        #pragma unroll
        for (int it = 0; it < 8; it++) {
            const int kb = it * 8;
            uint32_t af[2][4], bf[2][2];
            #pragma unroll
            for (int mt = 0; mt < 2; mt++) {
                const float* ap = Ab + (wj * 32 + mt * 16 + g) * 68 + kb + t;
                af[mt][0] = __float_as_uint(ap[0]);
                af[mt][1] = __float_as_uint(ap[8 * 68]);
                af[mt][2] = __float_as_uint(ap[4]);
                af[mt][3] = __float_as_uint(ap[8 * 68 + 4]);
            }
            #pragma unroll
            for (int nt = 0; nt < 2; nt++) {
                const float* bp = u_qd + (wq * 16 + nt * 8 + g) * 260 + c * 64 + kb + t;
                bf[nt][0] = __float_as_uint(bp[0]);
                bf[nt][1] = __float_as_uint(bp[4]);
            }
            #pragma unroll
            for (int mt = 0; mt < 2; mt++)
                #pragma unroll
                for (int nt = 0; nt < 2; nt++)
                    MMA_TF32(c1f[mt][nt], af[mt], bf[nt]);
        }
        // NOTE: no trailing sync; next iteration's STS targets the other buffer.
    }

    // ---- s_h ----
    shp += __shfl_xor_sync(0xffffffffu, shp, 1, 4);
    shp += __shfl_xor_sync(0xffffffffu, shp, 2, 4);
    if ((tid & 3) == 0) s_h[srow] = shp;

    // ---- store C1 fragments -> sp (must not race with last chunk's mma reads
    //      of A_s: sp != A_s, safe) ----
    #pragma unroll
    for (int mt = 0; mt < 2; mt++)
        #pragma unroll
        for (int nt = 0; nt < 2; nt++) {
            float* cp = sp + (wj * 32 + mt * 16 + g) * 68 + wq * 16 + nt * 8 + 2 * t;
            *(float2*)cp            = make_float2(c1f[mt][nt][0], c1f[mt][nt][1]);
            *(float2*)(cp + 8 * 68) = make_float2(c1f[mt][nt][2], c1f[mt][nt][3]);
        }
    __syncthreads();

    // ---- softmax over q, in place (thread: row srow, 16 q at soff) ----
    {
        float v[16];
        #pragma unroll
        for (int i = 0; i < 16; i++) v[i] = sp[srow * 68 + soff + i] + s_u[soff + i];
        float mx = v[0];
        #pragma unroll
        for (int i = 1; i < 16; i++) mx = fmaxf(mx, v[i]);
        mx = fmaxf(mx, __shfl_xor_sync(0xffffffffu, mx, 1, 4));
        mx = fmaxf(mx, __shfl_xor_sync(0xffffffffu, mx, 2, 4));
        float sum = 0.f;
        #pragma unroll
        for (int i = 0; i < 16; i++) { v[i] = __expf(v[i] - mx); sum += v[i]; }
        sum += __shfl_xor_sync(0xffffffffu, sum, 1, 4);
        sum += __shfl_xor_sync(0xffffffffu, sum, 2, 4);
        float inv = 1.f / sum;
        #pragma unroll
        for (int i = 0; i < 16; i++) sp[srow * 68 + soff + i] = f2tf(v[i] * inv);
        if ((tid & 3) == 0) s_pm[srow] = mx + s_h[srow];
    }
    __syncthreads();

    // ---- p = softmax_j(s_pm) (warp 0) ----
    if (wid == 0) {
        float v0 = s_pm[lane], v1 = s_pm[lane + 32], v2 = s_pm[lane + 64], v3 = s_pm[lane + 96];
        float mx = fmaxf(fmaxf(v0, v1), fmaxf(v2, v3));
        #pragma unroll
        for (int o = 16; o >= 1; o >>= 1) mx = fmaxf(mx, __shfl_xor_sync(0xffffffffu, mx, o));
        float e0 = __expf(v0 - mx), e1 = __expf(v1 - mx);
        float e2 = __expf(v2 - mx), e3 = __expf(v3 - mx);
        float s = e0 + e1 + e2 + e3;
        #pragma unroll
        for (int o = 16; o >= 1; o >>= 1) s += __shfl_xor_sync(0xffffffffu, s, o);
        float inv = 1.f / s;
        p_s[lane] = e0 * inv; p_s[lane + 32] = e1 * inv;
        p_s[lane + 64] = e2 * inv; p_s[lane + 96] = e3 * inv;
    }

    // ---- GEMM2: u_att[128 j][256 d] = P . u, K=64(q), 4 d-slabs of 64 ----
    // B fragments read directly from u_qd ([q][d], <=2-way bank conflicts).
    for (int s = 0; s < 4; s++) {
        // prefetch epilogue h for this slab (consumed after the D2 barrier)
        float4 hpre[4];
        #pragma unroll
        for (int i = 0; i < 4; i++)
            hpre[i] = *(const float4*)(hrow + srow * DN + s * 64 + soff + 4 * i);

        float d2f[2][2][4];
        #pragma unroll
        for (int mt = 0; mt < 2; mt++)
            #pragma unroll
            for (int nt = 0; nt < 2; nt++)
                #pragma unroll
                for (int i = 0; i < 4; i++) d2f[mt][nt][i] = 0.f;

        #pragma unroll
        for (int it = 0; it < 8; it++) {
            const int kb = it * 8;
            uint32_t af[2][4], bf[2][2];
            #pragma unroll
            for (int mt = 0; mt < 2; mt++) {
                const float* ap = sp + (wj * 32 + mt * 16 + g) * 68 + kb + t;
                af[mt][0] = __float_as_uint(ap[0]);
                af[mt][1] = __float_as_uint(ap[8 * 68]);
                af[mt][2] = __float_as_uint(ap[4]);
                af[mt][3] = __float_as_uint(ap[8 * 68 + 4]);
            }
            #pragma unroll
            for (int nt = 0; nt < 2; nt++) {
                // value(k=q, n=d) = u_qd[q*260 + d]; b0: q=kb+t, b1: q=kb+t+4
                const float* bp = u_qd + (kb + t) * 260 + s * 64 + wq * 16 + nt * 8 + g;
                bf[nt][0] = __float_as_uint(bp[0]);
                bf[nt][1] = __float_as_uint(bp[4 * 260]);
            }
            #pragma unroll
            for (int mt = 0; mt < 2; mt++)
                #pragma unroll
                for (int nt = 0; nt < 2; nt++)
                    MMA_TF32(d2f[mt][nt], af[mt], bf[nt]);
        }
        // fragments -> D2 bounce buffer
        #pragma unroll
        for (int mt = 0; mt < 2; mt++)
            #pragma unroll
            for (int nt = 0; nt < 2; nt++) {
                float* cp = D2 + (wj * 32 + mt * 16 + g) * 68 + wq * 16 + nt * 8 + 2 * t;
                *(float2*)cp            = make_float2(d2f[mt][nt][0], d2f[mt][nt][1]);
                *(float2*)(cp + 8 * 68) = make_float2(d2f[mt][nt][2], d2f[mt][nt][3]);
            }
        __syncthreads();
        // coalesced epilogue for this d-slab: segments 0,1,2 (h from prefetch)
        {
            float* ob = out + outbase + (size_t)srow * (4 * DN);
            #pragma unroll
            for (int i = 0; i < 4; i++) {
                const int dl = soff + 4 * i;
                const int dgl = s * 64 + dl;
                float4 ua = make_float4(D2[srow * 68 + dl + 0], D2[srow * 68 + dl + 1],
                                        D2[srow * 68 + dl + 2], D2[srow * 68 + dl + 3]);
                float4 h4 = hpre[i];
                float4 hu = make_float4(h4.x * ua.x, h4.y * ua.y, h4.z * ua.z, h4.w * ua.w);
                *(float4*)(ob + dgl)            = h4;   // segment 0: h
                *(float4*)(ob + DN + dgl)       = ua;   // segment 1: u_att
                *(float4*)(ob + 2 * DN + dgl)   = hu;   // segment 2: h*u_att
            }
        }
        __syncthreads();
    }

    // ---- h_att = sum_j p_j h[j,:]; write segment 3 ----
    {
        const int jg = tid >> 6, dq = tid & 63;
        float4 acc = make_float4(0.f, 0.f, 0.f, 0.f);
        #pragma unroll 4
        for (int j = jg * 16; j < jg * 16 + 16; j++) {
            float4 hv = *(const float4*)(hrow + j * DN + dq * 4);
            float pj = p_s[j];
            acc.x += pj * hv.x; acc.y += pj * hv.y; acc.z += pj * hv.z; acc.w += pj * hv.w;
        }
        part[jg * 64 + dq] = acc;
        __syncthreads();
        if (tid < 64) {
            float4 sacc = part[tid];
            #pragma unroll
            for (int gg = 1; gg < 8; gg++) {
                float4 v = part[gg * 64 + tid];
                sacc.x += v.x; sacc.y += v.y; sacc.z += v.z; sacc.w += v.w;
            }
            part[tid] = sacc;
        }
        __syncthreads();
        const float4 ha = part[dq];
        #pragma unroll 2
        for (int j = jg * 16; j < jg * 16 + 16; j++) {
            float4 hv = *(const float4*)(hrow + j * DN + dq * 4);
            float4 o;
            o.x = hv.x * ha.x; o.y = hv.y * ha.y; o.z = hv.z * ha.z; o.w = hv.w * ha.w;
            *(float4*)(out + outbase + (size_t)j * (4 * DN) + 3 * DN + dq * 4) = o;
        }
    }
}

// ---------------------------------------------------------------------------
extern "C" void kernel_launch(void* const* d_in, const int* in_sizes, int n_in,
                              void* d_out, int out_size)
{
    (void)in_sizes; (void)n_in; (void)out_size;
    const float* h = (const float*)d_in[0];
    const float* u = (const float*)d_in[1];
    const float* w = (const float*)d_in[2];
    // d_in[3] (scalar bias b) cancels in both softmaxes -> unused.
    float* out = (float*)d_out;

    const size_t smem = SMEM_FLOATS * sizeof(float);   // 218,880 B
    cudaFuncSetAttribute(attn_mma, cudaFuncAttributeMaxDynamicSharedMemorySize, (int)smem);
    attn_mma<<<BB * MM, 512, smem>>>(h, u, w, out);
}